// round 14
// baseline (speedup 1.0000x reference)
#include <cuda_runtime.h>
#include <cuda_bf16.h>
#include <math.h>
#include <stdint.h>

#define SLEN   1024
#define DMODEL 1024
#define NHEAD  16
#define DHEAD  64
#define NC     64
#define CHUNK  64
#define NCHUNK 16
#define SP     68      // smem row stride (floats): 272B, 16B-aligned

// ---------------- global scratch ----------------
__device__ float g_Q[SLEN*DMODEL];
__device__ float g_K[SLEN*DMODEL];
__device__ float g_V[SLEN*DMODEL];
__device__ float g_cw[NHEAD*NC*SLEN];
__device__ float g_Tk[NHEAD*NCHUNK*NC*DHEAD];
__device__ float g_Tv[NHEAD*NCHUNK*NC*DHEAD];
__device__ float g_Tn[NHEAD*NCHUNK*NC];
__device__ float g_A0k[NHEAD*NCHUNK*NC*DHEAD];
__device__ float g_A0v[NHEAD*NCHUNK*NC*DHEAD];
__device__ float g_N0[NHEAD*NCHUNK*NC];

// bf16 hi/lo split buffers
__device__ __nv_bfloat16 g_xh[SLEN*DMODEL],  g_xl[SLEN*DMODEL];
__device__ __nv_bfloat16 g_Wqh[DMODEL*DMODEL], g_Wql[DMODEL*DMODEL];
__device__ __nv_bfloat16 g_Wkh[DMODEL*DMODEL], g_Wkl[DMODEL*DMODEL];
__device__ __nv_bfloat16 g_Wvh[DMODEL*DMODEL], g_Wvl[DMODEL*DMODEL];
__device__ __nv_bfloat16 g_Woh[DMODEL*DMODEL], g_Wol[DMODEL*DMODEL];
__device__ __nv_bfloat16 g_Oh[SLEN*DMODEL],  g_Ol[SLEN*DMODEL];

__device__ __forceinline__ uint32_t pack_bf2(__nv_bfloat16 a, __nv_bfloat16 b) {
    return (uint32_t)__bfloat16_as_ushort(a) | ((uint32_t)__bfloat16_as_ushort(b) << 16);
}

// ---------------- split fp32 -> bf16 hi/lo ----------------
__device__ __forceinline__ void split_one(const float* __restrict__ src,
                                          __nv_bfloat16* __restrict__ dh,
                                          __nv_bfloat16* __restrict__ dl,
                                          int i)
{
    float4 v = *(const float4*)(src + i);
    __nv_bfloat16 h0 = __float2bfloat16_rn(v.x), h1 = __float2bfloat16_rn(v.y);
    __nv_bfloat16 h2 = __float2bfloat16_rn(v.z), h3 = __float2bfloat16_rn(v.w);
    uint2 hp = make_uint2(pack_bf2(h0, h1), pack_bf2(h2, h3));
    uint2 lp = make_uint2(
        pack_bf2(__float2bfloat16_rn(v.x - __bfloat162float(h0)),
                 __float2bfloat16_rn(v.y - __bfloat162float(h1))),
        pack_bf2(__float2bfloat16_rn(v.z - __bfloat162float(h2)),
                 __float2bfloat16_rn(v.w - __bfloat162float(h3))));
    *(uint2*)(dh + i) = hp;
    *(uint2*)(dl + i) = lp;
}

__global__ __launch_bounds__(256) void split3_kernel(
    const float* __restrict__ x,
    const float* __restrict__ Wk, const float* __restrict__ Wv)
{
    const int z = blockIdx.y;
    const float* src = (z == 0) ? x : (z == 1) ? Wk : Wv;
    __nv_bfloat16* dh = (z == 0) ? g_xh : (z == 1) ? g_Wkh : g_Wvh;
    __nv_bfloat16* dl = (z == 0) ? g_xl : (z == 1) ? g_Wkl : g_Wvl;
    split_one(src, dh, dl, (blockIdx.x * 256 + threadIdx.x) * 4);
}

__global__ __launch_bounds__(256) void splitWq_kernel(const float* __restrict__ Wq)
{
    split_one(Wq, g_Wqh, g_Wql, (blockIdx.x * 256 + threadIdx.x) * 4);
}

__global__ __launch_bounds__(256) void splitWo_kernel(const float* __restrict__ Wo)
{
    split_one(Wo, g_Woh, g_Wol, (blockIdx.x * 256 + threadIdx.x) * 4);
}

// =================== bf16 split-precision HMMA GEMM ===================
#define KT    32
#define KPAD  40
#define CP_ASYNC16(dst, src) \
    asm volatile("cp.async.cg.shared.global [%0], [%1], 16;" :: "r"(dst), "l"(src))
#define CP_COMMIT() asm volatile("cp.async.commit_group;" ::: "memory")
#define CP_WAIT1()  asm volatile("cp.async.wait_group 1;" ::: "memory")
#define CP_WAIT0()  asm volatile("cp.async.wait_group 0;" ::: "memory")

#define LDSM4(r0, r1, r2, r3, addr) \
    asm volatile("ldmatrix.sync.aligned.m8n8.x4.shared.b16 {%0,%1,%2,%3}, [%4];" \
        : "=r"(r0), "=r"(r1), "=r"(r2), "=r"(r3) : "r"(addr))

__device__ __forceinline__ uint32_t smem_u32(const void* p) {
    uint32_t a;
    asm("{ .reg .u64 t; cvta.to.shared.u64 t, %1; cvt.u32.u64 %0, t; }" : "=r"(a) : "l"(p));
    return a;
}

__device__ __forceinline__ void mma_bf16(float* c, const uint32_t* a, const uint32_t* b)
{
    asm volatile(
        "mma.sync.aligned.m16n8k16.row.col.f32.bf16.bf16.f32 "
        "{%0,%1,%2,%3}, {%4,%5,%6,%7}, {%8,%9}, {%0,%1,%2,%3};"
        : "+f"(c[0]), "+f"(c[1]), "+f"(c[2]), "+f"(c[3])
        : "r"(a[0]), "r"(a[1]), "r"(a[2]), "r"(a[3]), "r"(b[0]), "r"(b[1]));
}

template<int MROWS>
__device__ __forceinline__ void tc_prefetch(
    const __nv_bfloat16* __restrict__ Ah, const __nv_bfloat16* __restrict__ Al,
    const __nv_bfloat16* __restrict__ Bh, const __nv_bfloat16* __restrict__ Bl,
    int m0, int n0, int k0, uint32_t sdst, int tid)
{
    const int ARR_A = MROWS * KPAD * 2;
    const int ARR_BB = 128 * KPAD * 2;
#pragma unroll
    for (int i = 0; i < (MROWS * 4) / 256; ++i) {
        int idx = tid + i * 256;
        int row = idx >> 2, ch = idx & 3;
        uint32_t doff = (uint32_t)(row * (KPAD * 2) + ch * 16);
        size_t aoff = (size_t)(m0 + row) * DMODEL + k0 + ch * 8;
        CP_ASYNC16(sdst + doff,          Ah + aoff);
        CP_ASYNC16(sdst + ARR_A + doff,  Al + aoff);
    }
#pragma unroll
    for (int i = 0; i < 2; ++i) {
        int idx = tid + i * 256;
        int row = idx >> 2, ch = idx & 3;
        uint32_t doff = (uint32_t)(row * (KPAD * 2) + ch * 16);
        size_t boff = (size_t)(n0 + row) * DMODEL + k0 + ch * 8;
        CP_ASYNC16(sdst + 2*ARR_A + doff,          Bh + boff);
        CP_ASYNC16(sdst + 2*ARR_A + ARR_BB + doff, Bl + boff);
    }
}

template<int MROWS>   // 128 or 64
__device__ void tc_gemm_body(
    const __nv_bfloat16* __restrict__ Ah, const __nv_bfloat16* __restrict__ Al,
    const __nv_bfloat16* __restrict__ Bh, const __nv_bfloat16* __restrict__ Bl,
    const float* __restrict__ bias, float* __restrict__ Cout)
{
    extern __shared__ char smem[];
    const int MI = MROWS / 32;
    const int ARR_A = MROWS * KPAD * 2;
    const int STG = 2 * ARR_A + 2 * 128 * KPAD * 2;
    const int tid  = threadIdx.x;
    const int wid  = tid >> 5;
    const int lane = tid & 31;
    const int m0 = blockIdx.y * MROWS, n0 = blockIdx.x << 7;
    const int wm = (wid >> 2) * (MROWS / 2);
    const int wn = (wid & 3) * 32;
    const int lrow = lane >> 2;
    const int lk2  = (lane & 3) << 1;
    const uint32_t sb = smem_u32(smem);

    const int a_lane_off = (lane & 15) * KPAD + ((lane >= 16) ? 8 : 0);
    const int b_lane_off = ((lane & 7) + ((lane >= 16) ? 8 : 0)) * KPAD
                         + (((lane & 15) >= 8) ? 8 : 0);

    float acc[MI][4][4];
#pragma unroll
    for (int i = 0; i < MI; ++i)
#pragma unroll
        for (int j = 0; j < 4; ++j)
#pragma unroll
            for (int e = 0; e < 4; ++e) acc[i][j][e] = 0.f;

    tc_prefetch<MROWS>(Ah, Al, Bh, Bl, m0, n0, 0, sb, tid);
    CP_COMMIT();

    const int NKT = DMODEL / KT;
    for (int kt = 0; kt < NKT; ++kt) {
        if (kt + 1 < NKT) {
            tc_prefetch<MROWS>(Ah, Al, Bh, Bl, m0, n0, (kt + 1) * KT,
                               sb + ((kt + 1) & 1) * STG, tid);
            CP_COMMIT();
            CP_WAIT1();
        } else {
            CP_WAIT0();
        }
        __syncthreads();

        const uint32_t sAh32 = sb + (kt & 1) * STG;
        const uint32_t sAl32 = sAh32 + (uint32_t)(MROWS * KPAD * 2);
        const uint32_t sBh32 = sAh32 + (uint32_t)(2 * MROWS * KPAD * 2);
        const uint32_t sBl32 = sBh32 + (uint32_t)(128 * KPAD * 2);

#pragma unroll
        for (int kk = 0; kk < KT; kk += 16) {
            uint32_t ah[MI][4], al[MI][4], bh[4][2], bl[4][2];
#pragma unroll
            for (int mt = 0; mt < MI; ++mt) {
                uint32_t off = (uint32_t)(((wm + mt * 16) * KPAD + kk + a_lane_off) * 2);
                LDSM4(ah[mt][0], ah[mt][1], ah[mt][2], ah[mt][3], sAh32 + off);
                LDSM4(al[mt][0], al[mt][1], al[mt][2], al[mt][3], sAl32 + off);
            }
#pragma unroll
            for (int np = 0; np < 2; ++np) {
                uint32_t off = (uint32_t)(((wn + np * 16) * KPAD + kk + b_lane_off) * 2);
                LDSM4(bh[2*np][0], bh[2*np][1], bh[2*np+1][0], bh[2*np+1][1], sBh32 + off);
                LDSM4(bl[2*np][0], bl[2*np][1], bl[2*np+1][0], bl[2*np+1][1], sBl32 + off);
            }
#pragma unroll
            for (int mt = 0; mt < MI; ++mt)
#pragma unroll
                for (int nt = 0; nt < 4; ++nt) {
                    mma_bf16(acc[mt][nt], ah[mt], bh[nt]);
                    mma_bf16(acc[mt][nt], ah[mt], bl[nt]);
                    mma_bf16(acc[mt][nt], al[mt], bh[nt]);
                }
        }
        __syncthreads();
    }

#pragma unroll
    for (int mt = 0; mt < MI; ++mt) {
#pragma unroll
        for (int nt = 0; nt < 4; ++nt) {
            int r  = m0 + wm + mt * 16 + lrow;
            int cc = n0 + wn + nt * 8 + lk2;
            float2 bz = *(const float2*)&bias[cc];
            float2 v0 = make_float2(acc[mt][nt][0] + bz.x, acc[mt][nt][1] + bz.y);
            float2 v1 = make_float2(acc[mt][nt][2] + bz.x, acc[mt][nt][3] + bz.y);
            *(float2*)&Cout[(size_t)r * DMODEL + cc]       = v0;
            *(float2*)&Cout[(size_t)(r + 8) * DMODEL + cc] = v1;
        }
    }
}

#define GSMEM128 (2 * (4 * 128 * KPAD * 2))
#define GSMEM64  (2 * (2 * 64 * KPAD * 2 + 2 * 128 * KPAD * 2))

__global__ __launch_bounds__(256, 2)
void tc_gemm_kv_kernel(const float* __restrict__ bk, const float* __restrict__ bv)
{
    int z = blockIdx.z;
    const __nv_bfloat16* Bh = (z == 0) ? g_Wkh : g_Wvh;
    const __nv_bfloat16* Bl = (z == 0) ? g_Wkl : g_Wvl;
    const float* b = (z == 0) ? bk : bv;
    float* out = (z == 0) ? g_K : g_V;
    tc_gemm_body<128>(g_xh, g_xl, Bh, Bl, b, out);
}

__global__ __launch_bounds__(256, 2)
void tc_gemm_q_kernel(const float* __restrict__ bq)
{
    tc_gemm_body<128>(g_xh, g_xl, g_Wqh, g_Wql, bq, g_Q);
}

__global__ __launch_bounds__(256, 2)
void tc_gemm_o_kernel(const float* __restrict__ bo, float* __restrict__ out)
{
    tc_gemm_body<64>(g_Oh, g_Ol, g_Woh, g_Wol, bo, out);
}

// ======================= fused cw + exp + chunksum =======================
struct ChunkSmem {
    float qcsT[DHEAD][SP];  // [d][c]
    float KsT[DHEAD][SP];   // [d][t]
    float Ks[CHUNK][SP];    // [t][d]
    float Vs[CHUNK][SP];    // [t][d]
    float cwsT[CHUNK][SP];  // [t][c]  (exp'd)
};

__global__ __launch_bounds__(256) void chunksum_kernel(const float* __restrict__ q_c)
{
    extern __shared__ char smem_raw[];
    ChunkSmem& sm = *(ChunkSmem*)smem_raw;
    const int h = blockIdx.y, ch = blockIdx.x;
    const int s0 = ch * CHUNK;
    const int tid = threadIdx.x;
    const int tx = tid & 15, ty = tid >> 4;

    for (int e = tid; e < NC * CHUNK; e += 256) {
        int r = e >> 6, d = e & 63;
        sm.qcsT[d][r] = q_c[(size_t)r * DMODEL + h * DHEAD + d];
        float kv = g_K[(size_t)(s0 + r) * DMODEL + h * DHEAD + d];
        sm.KsT[d][r] = kv;
        sm.Ks[r][d]  = kv;
        sm.Vs[r][d]  = g_V[(size_t)(s0 + r) * DMODEL + h * DHEAD + d];
    }
    __syncthreads();

    // cw[c][t] = exp( qc[c,:].K[t,:] )
    {
        float acc[4][4];
#pragma unroll
        for (int i = 0; i < 4; ++i)
#pragma unroll
            for (int j = 0; j < 4; ++j) acc[i][j] = 0.f;
#pragma unroll 4
        for (int d = 0; d < DHEAD; ++d) {
            float4 a4 = *(const float4*)&sm.qcsT[d][ty << 2];
            float4 b4 = *(const float4*)&sm.KsT[d][tx << 2];
            float ar[4] = {a4.x, a4.y, a4.z, a4.w};
            float br[4] = {b4.x, b4.y, b4.z, b4.w};
#pragma unroll
            for (int i = 0; i < 4; ++i)
#pragma unroll
                for (int j = 0; j < 4; ++j) acc[i][j] = fmaf(ar[i], br[j], acc[i][j]);
        }
#pragma unroll
        for (int i = 0; i < 4; ++i) {
            int c = (ty << 2) + i;
#pragma unroll
            for (int j = 0; j < 4; ++j) {
                int t = (tx << 2) + j;
                float v = expf(acc[i][j]);
                sm.cwsT[t][c] = v;
                g_cw[((size_t)h * NC + c) * SLEN + s0 + t] = v;
            }
        }
    }
    __syncthreads();

    float ak[4][4], av[4][4];
#pragma unroll
    for (int i = 0; i < 4; ++i)
#pragma unroll
        for (int j = 0; j < 4; ++j) { ak[i][j] = 0.f; av[i][j] = 0.f; }

#pragma unroll 4
    for (int t = 0; t < CHUNK; ++t) {
        float4 a4 = *(const float4*)&sm.cwsT[t][ty << 2];
        float4 k4 = *(const float4*)&sm.Ks[t][tx << 2];
        float4 v4 = *(const float4*)&sm.Vs[t][tx << 2];
        float ar[4] = {a4.x, a4.y, a4.z, a4.w};
        float bk[4] = {k4.x, k4.y, k4.z, k4.w};
        float bv[4] = {v4.x, v4.y, v4.z, v4.w};
#pragma unroll
        for (int i = 0; i < 4; ++i)
#pragma unroll
            for (int j = 0; j < 4; ++j) {
                ak[i][j] = fmaf(ar[i], bk[j], ak[i][j]);
                av[i][j] = fmaf(ar[i], bv[j], av[i][j]);
            }
    }
    const size_t base = ((size_t)(h * NCHUNK + ch) * NC) * DHEAD;
#pragma unroll
    for (int i = 0; i < 4; ++i) {
        int c = (ty << 2) + i;
#pragma unroll
        for (int j = 0; j < 4; ++j) {
            int d = (tx << 2) + j;
            g_Tk[base + (size_t)c * DHEAD + d] = ak[i][j];
            g_Tv[base + (size_t)c * DHEAD + d] = av[i][j];
        }
    }
    if (tid < NC) {
        float s = 0.f;
#pragma unroll
        for (int t = 0; t < CHUNK; ++t) s += sm.cwsT[t][tid];
        g_Tn[(size_t)(h * NCHUNK + ch) * NC + tid] = s;
    }
}

// ---------------- parallel exclusive prefix over chunks ----------------
__global__ __launch_bounds__(256) void prefix_kernel()
{
    const int gid = blockIdx.x * 256 + threadIdx.x;
    if (blockIdx.x < 256) {
        const int h = gid >> 12;
        const int e = gid & 4095;
        const size_t base0 = ((size_t)h * NCHUNK * NC) * DHEAD + e;
        const size_t cstep = (size_t)NC * DHEAD;
        float tk[NCHUNK], tv[NCHUNK];
#pragma unroll
        for (int ch = 0; ch < NCHUNK; ++ch) {
            tk[ch] = g_Tk[base0 + ch * cstep];
            tv[ch] = g_Tv[base0 + ch * cstep];
        }
        float rk = 0.f, rv = 0.f;
#pragma unroll
        for (int ch = 0; ch < NCHUNK; ++ch) {
            g_A0k[base0 + ch * cstep] = rk; rk += tk[ch];
            g_A0v[base0 + ch * cstep] = rv; rv += tv[ch];
        }
    } else {
        const int e = (blockIdx.x - 256) * 256 + threadIdx.x;  // h*NC + c
        const int h = e >> 6;
        const int c = e & 63;
        const size_t base0 = (size_t)h * NCHUNK * NC + c;
        float tn[NCHUNK];
#pragma unroll
        for (int ch = 0; ch < NCHUNK; ++ch) tn[ch] = g_Tn[base0 + ch * NC];
        float rn = 0.f;
#pragma unroll
        for (int ch = 0; ch < NCHUNK; ++ch) { g_N0[base0 + ch * NC] = rn; rn += tn[ch]; }
    }
}

// ---------------- per-(head,chunk) attention (vectorized) --------------
struct K7Smem {
    float QsT[DHEAD][SP];   // [d][s]  (pre-scaled)
    float KsT[DHEAD][SP];   // [d][t]
    float Vs[CHUNK][SP];    // [t][d]
    float cwsN[NC][SP];     // [c][t]
    float cwsT[CHUNK][SP];  // [t][c]
    float ncs[NC][SP];      // [c][s]
    float A0kT[DHEAD][SP];  // [d][c]
    float A0v[NC][SP];      // [c][d]
    float GT[CHUNK][SP];    // [t][s]
    float PT[NC][SP];       // [c][s]
    float n0v[NC];
};

__global__ __launch_bounds__(256) void attn_kernel(const float* __restrict__ beta)
{
    extern __shared__ char smem_raw[];
    K7Smem& sm = *(K7Smem*)smem_raw;
    const int h = blockIdx.y, ch = blockIdx.x;
    const int s0 = ch * CHUNK;
    const int tid = threadIdx.x;
    const int tx = tid & 15, ty = tid >> 4;
    const float qscale = 0.125f * expf(-beta[h]);

    const size_t abase = ((size_t)(h * NCHUNK + ch) * NC) * DHEAD;
    for (int e = tid; e < CHUNK * DHEAD; e += 256) {
        int r = e >> 6, d = e & 63;
        sm.QsT[d][r] = g_Q[(size_t)(s0 + r) * DMODEL + h * DHEAD + d] * qscale;
        sm.KsT[d][r] = g_K[(size_t)(s0 + r) * DMODEL + h * DHEAD + d];
        sm.Vs[r][d]  = g_V[(size_t)(s0 + r) * DMODEL + h * DHEAD + d];
        float cv = g_cw[((size_t)h * NC + r) * SLEN + s0 + d];
        sm.cwsN[r][d] = cv;
        sm.cwsT[d][r] = cv;
        sm.A0kT[d][r] = g_A0k[abase + e];
        sm.A0v[r][d]  = g_A0v[abase + e];
    }
    if (tid < NC) sm.n0v[tid] = g_N0[(size_t)(h * NCHUNK + ch) * NC + tid];
    __syncthreads();

    if (tid < NC) {
        float run = sm.n0v[tid];
#pragma unroll
        for (int t = 0; t < CHUNK; ++t) { run += sm.cwsN[tid][t]; sm.ncs[tid][t] = run; }
    }

    // G[t][s] = (t<=s) ? Qs[s].Ks[t] : 0
    {
        float acc[4][4];
#pragma unroll
        for (int i = 0; i < 4; ++i)
#pragma unroll
            for (int j = 0; j < 4; ++j) acc[i][j] = 0.f;
#pragma unroll 4
        for (int d = 0; d < DHEAD; ++d) {
            float4 a4 = *(const float4*)&sm.QsT[d][ty << 2];
            float4 b4 = *(const float4*)&sm.KsT[d][tx << 2];
            float ar[4] = {a4.x, a4.y, a4.z, a4.w};
            float br[4] = {b4.x, b4.y, b4.z, b4.w};
#pragma unroll
            for (int i = 0; i < 4; ++i)
#pragma unroll
                for (int j = 0; j < 4; ++j) acc[i][j] = fmaf(ar[i], br[j], acc[i][j]);
        }
#pragma unroll
        for (int i = 0; i < 4; ++i) {
            int s = (ty << 2) + i;
#pragma unroll
            for (int j = 0; j < 4; ++j) {
                int t = (tx << 2) + j;
                sm.GT[t][s] = (t <= s) ? acc[i][j] : 0.f;
            }
        }
    }
    __syncthreads();

    // P[c][s] = (Qs[s].A0k[c] + sum_t G[t][s]*cwT[t][c]) / ncs[c][s]
    {
        float acc[4][4];
#pragma unroll
        for (int i = 0; i < 4; ++i)
#pragma unroll
            for (int j = 0; j < 4; ++j) acc[i][j] = 0.f;
#pragma unroll 4
        for (int d = 0; d < DHEAD; ++d) {
            float4 a4 = *(const float4*)&sm.QsT[d][ty << 2];
            float4 b4 = *(const float4*)&sm.A0kT[d][tx << 2];
            float ar[4] = {a4.x, a4.y, a4.z, a4.w};
            float br[4] = {b4.x, b4.y, b4.z, b4.w};
#pragma unroll
            for (int i = 0; i < 4; ++i)
#pragma unroll
                for (int j = 0; j < 4; ++j) acc[i][j] = fmaf(ar[i], br[j], acc[i][j]);
        }
#pragma unroll 4
        for (int t = 0; t < CHUNK; ++t) {
            float4 a4 = *(const float4*)&sm.GT[t][ty << 2];
            float4 b4 = *(const float4*)&sm.cwsT[t][tx << 2];
            float ar[4] = {a4.x, a4.y, a4.z, a4.w};
            float br[4] = {b4.x, b4.y, b4.z, b4.w};
#pragma unroll
            for (int i = 0; i < 4; ++i)
#pragma unroll
                for (int j = 0; j < 4; ++j) acc[i][j] = fmaf(ar[i], br[j], acc[i][j]);
        }
#pragma unroll
        for (int i = 0; i < 4; ++i) {
            int s = (ty << 2) + i;
#pragma unroll
            for (int j = 0; j < 4; ++j) {
                int c = (tx << 2) + j;
                sm.PT[c][s] = acc[i][j] / sm.ncs[c][s];
            }
        }
    }
    __syncthreads();

    // softmax over c per s, then /ncs
    if (tid < CHUNK) {
        int s = tid;
        float m = -INFINITY;
#pragma unroll
        for (int c = 0; c < NC; ++c) m = fmaxf(m, sm.PT[c][s]);
        float sum = 0.f;
#pragma unroll
        for (int c = 0; c < NC; ++c) { float e = expf(sm.PT[c][s] - m); sm.PT[c][s] = e; sum += e; }
        float inv = 1.f / sum;
#pragma unroll
        for (int c = 0; c < NC; ++c) sm.PT[c][s] = sm.PT[c][s] * inv / sm.ncs[c][s];
    }
    __syncthreads();

    // W[t][s] = (t<=s) ? sum_c P[c][s]*cwN[c][t] : 0   (into GT)
    {
        float acc[4][4];
#pragma unroll
        for (int i = 0; i < 4; ++i)
#pragma unroll
            for (int j = 0; j < 4; ++j) acc[i][j] = 0.f;
#pragma unroll 4
        for (int c = 0; c < NC; ++c) {
            float4 a4 = *(const float4*)&sm.PT[c][ty << 2];
            float4 b4 = *(const float4*)&sm.cwsN[c][tx << 2];
            float ar[4] = {a4.x, a4.y, a4.z, a4.w};
            float br[4] = {b4.x, b4.y, b4.z, b4.w};
#pragma unroll
            for (int i = 0; i < 4; ++i)
#pragma unroll
                for (int j = 0; j < 4; ++j) acc[i][j] = fmaf(ar[i], br[j], acc[i][j]);
        }
        __syncthreads();
#pragma unroll
        for (int i = 0; i < 4; ++i) {
            int s = (ty << 2) + i;
#pragma unroll
            for (int j = 0; j < 4; ++j) {
                int t = (tx << 2) + j;
                sm.GT[t][s] = (t <= s) ? acc[i][j] : 0.f;
            }
        }
    }
    __syncthreads();

    // O[s][d] = sum_t W[t][s]*V[t][d] + sum_c P[c][s]*A0v[c][d]
    {
        float acc[4][4];
#pragma unroll
        for (int i = 0; i < 4; ++i)
#pragma unroll
            for (int j = 0; j < 4; ++j) acc[i][j] = 0.f;
#pragma unroll 4
        for (int t = 0; t < CHUNK; ++t) {
            float4 a4 = *(const float4*)&sm.GT[t][ty << 2];
            float4 b4 = *(const float4*)&sm.Vs[t][tx << 2];
            float ar[4] = {a4.x, a4.y, a4.z, a4.w};
            float br[4] = {b4.x, b4.y, b4.z, b4.w};
#pragma unroll
            for (int i = 0; i < 4; ++i)
#pragma unroll
                for (int j = 0; j < 4; ++j) acc[i][j] = fmaf(ar[i], br[j], acc[i][j]);
        }
#pragma unroll 4
        for (int c = 0; c < NC; ++c) {
            float4 a4 = *(const float4*)&sm.PT[c][ty << 2];
            float4 b4 = *(const float4*)&sm.A0v[c][tx << 2];
            float ar[4] = {a4.x, a4.y, a4.z, a4.w};
            float br[4] = {b4.x, b4.y, b4.z, b4.w};
#pragma unroll
            for (int i = 0; i < 4; ++i)
#pragma unroll
                for (int j = 0; j < 4; ++j) acc[i][j] = fmaf(ar[i], br[j], acc[i][j]);
        }
        // write O directly as bf16 hi/lo pairs for the Wo GEMM
#pragma unroll
        for (int i = 0; i < 4; ++i) {
            int s = (ty << 2) + i;
            size_t rowoff = (size_t)(s0 + s) * DMODEL + h * DHEAD + (tx << 2);
            __nv_bfloat16 h0 = __float2bfloat16_rn(acc[i][0]);
            __nv_bfloat16 h1 = __float2bfloat16_rn(acc[i][1]);
            __nv_bfloat16 h2 = __float2bfloat16_rn(acc[i][2]);
            __nv_bfloat16 h3 = __float2bfloat16_rn(acc[i][3]);
            *(uint32_t*)&g_Oh[rowoff]     = pack_bf2(h0, h1);
            *(uint32_t*)&g_Oh[rowoff + 2] = pack_bf2(h2, h3);
            *(uint32_t*)&g_Ol[rowoff] =
                pack_bf2(__float2bfloat16_rn(acc[i][0] - __bfloat162float(h0)),
                         __float2bfloat16_rn(acc[i][1] - __bfloat162float(h1)));
            *(uint32_t*)&g_Ol[rowoff + 2] =
                pack_bf2(__float2bfloat16_rn(acc[i][2] - __bfloat162float(h2)),
                         __float2bfloat16_rn(acc[i][3] - __bfloat162float(h3)));
        }
    }
}

// ---------------- launch -----------------------------------------------
extern "C" void kernel_launch(void* const* d_in, const int* in_sizes, int n_in,
                              void* d_out, int out_size)
{
    const float* x    = (const float*)d_in[0];
    const float* q_c  = (const float*)d_in[1];
    const float* beta = (const float*)d_in[2];
    const float* Wq   = (const float*)d_in[3];
    const float* bq   = (const float*)d_in[4];
    const float* Wk   = (const float*)d_in[5];
    const float* bk   = (const float*)d_in[6];
    const float* Wv   = (const float*)d_in[7];
    const float* bv   = (const float*)d_in[8];
    const float* Wo   = (const float*)d_in[9];
    const float* bo   = (const float*)d_in[10];
    float* out = (float*)d_out;

    static bool inited = false;
    static cudaStream_t s2;
    static cudaEvent_t evFork, evQ;
    if (!inited) {
        cudaFuncSetAttribute(attn_kernel, cudaFuncAttributeMaxDynamicSharedMemorySize,
                             (int)sizeof(K7Smem));
        cudaFuncSetAttribute(chunksum_kernel, cudaFuncAttributeMaxDynamicSharedMemorySize,
                             (int)sizeof(ChunkSmem));
        cudaFuncSetAttribute(tc_gemm_kv_kernel, cudaFuncAttributeMaxDynamicSharedMemorySize, GSMEM128);
        cudaFuncSetAttribute(tc_gemm_q_kernel, cudaFuncAttributeMaxDynamicSharedMemorySize, GSMEM128);
        cudaFuncSetAttribute(tc_gemm_o_kernel, cudaFuncAttributeMaxDynamicSharedMemorySize, GSMEM64);
        cudaStreamCreateWithFlags(&s2, cudaStreamNonBlocking);
        cudaEventCreateWithFlags(&evFork, cudaEventDisableTiming);
        cudaEventCreateWithFlags(&evQ, cudaEventDisableTiming);
        inited = true;
    }

    // main stream: split x, Wk, Wv (only what KV GEMM needs)
    split3_kernel<<<dim3(1024, 3), 256>>>(x, Wk, Wv);

    // fork BEFORE the KV GEMM: Q path depends only on x split
    cudaEventRecord(evFork, 0);
    cudaStreamWaitEvent(s2, evFork, 0);
    splitWq_kernel<<<1024, 256, 0, s2>>>(Wq);
    tc_gemm_q_kernel<<<dim3(8, 8), 256, GSMEM128, s2>>>(bq);
    splitWo_kernel<<<1024, 256, 0, s2>>>(Wo);
    cudaEventRecord(evQ, s2);

    // main stream: KV GEMM (overlaps Q GEMM), then chunksum + prefix
    tc_gemm_kv_kernel<<<dim3(8, 8, 2), 256, GSMEM128>>>(bk, bv);
    chunksum_kernel<<<dim3(NCHUNK, NHEAD), 256, sizeof(ChunkSmem)>>>(q_c);
    prefix_kernel<<<260, 256>>>();

    // join: attn needs Q + prefix; Wo GEMM needs Wo split + attn
    cudaStreamWaitEvent(0, evQ, 0);
    attn_kernel<<<dim3(NCHUNK, NHEAD), 256, sizeof(K7Smem)>>>(beta);
    tc_gemm_o_kernel<<<dim3(8, 16), 256, GSMEM64>>>(bo, out);
}

// round 15
// speedup vs baseline: 1.0627x; 1.0627x over previous
#include <cuda_runtime.h>
#include <cuda_bf16.h>
#include <math.h>
#include <stdint.h>

#define SLEN   1024
#define DMODEL 1024
#define NHEAD  16
#define DHEAD  64
#define NC     64
#define CHUNK  64
#define NCHUNK 16
#define SP     68      // smem row stride (floats): 272B, 16B-aligned

// ---------------- global scratch ----------------
__device__ float g_Q[SLEN*DMODEL];
__device__ float g_K[SLEN*DMODEL];
__device__ float g_V[SLEN*DMODEL];
__device__ float g_cw[NHEAD*NC*SLEN];
__device__ float g_Tk[NHEAD*NCHUNK*NC*DHEAD];
__device__ float g_Tv[NHEAD*NCHUNK*NC*DHEAD];
__device__ float g_Tn[NHEAD*NCHUNK*NC];
__device__ float g_A0k[NHEAD*NCHUNK*NC*DHEAD];
__device__ float g_A0v[NHEAD*NCHUNK*NC*DHEAD];
__device__ float g_N0[NHEAD*NCHUNK*NC];

// bf16 hi/lo split buffers
__device__ __nv_bfloat16 g_xh[SLEN*DMODEL],  g_xl[SLEN*DMODEL];
__device__ __nv_bfloat16 g_Wqh[DMODEL*DMODEL], g_Wql[DMODEL*DMODEL];
__device__ __nv_bfloat16 g_Wkh[DMODEL*DMODEL], g_Wkl[DMODEL*DMODEL];
__device__ __nv_bfloat16 g_Wvh[DMODEL*DMODEL], g_Wvl[DMODEL*DMODEL];
__device__ __nv_bfloat16 g_Woh[DMODEL*DMODEL], g_Wol[DMODEL*DMODEL];
__device__ __nv_bfloat16 g_Oh[SLEN*DMODEL],  g_Ol[SLEN*DMODEL];

__device__ __forceinline__ uint32_t pack_bf2(__nv_bfloat16 a, __nv_bfloat16 b) {
    return (uint32_t)__bfloat16_as_ushort(a) | ((uint32_t)__bfloat16_as_ushort(b) << 16);
}

// ---------------- split fp32 -> bf16 hi/lo ----------------
__device__ __forceinline__ void split_one(const float* __restrict__ src,
                                          __nv_bfloat16* __restrict__ dh,
                                          __nv_bfloat16* __restrict__ dl,
                                          int i)
{
    float4 v = *(const float4*)(src + i);
    __nv_bfloat16 h0 = __float2bfloat16_rn(v.x), h1 = __float2bfloat16_rn(v.y);
    __nv_bfloat16 h2 = __float2bfloat16_rn(v.z), h3 = __float2bfloat16_rn(v.w);
    uint2 hp = make_uint2(pack_bf2(h0, h1), pack_bf2(h2, h3));
    uint2 lp = make_uint2(
        pack_bf2(__float2bfloat16_rn(v.x - __bfloat162float(h0)),
                 __float2bfloat16_rn(v.y - __bfloat162float(h1))),
        pack_bf2(__float2bfloat16_rn(v.z - __bfloat162float(h2)),
                 __float2bfloat16_rn(v.w - __bfloat162float(h3))));
    *(uint2*)(dh + i) = hp;
    *(uint2*)(dl + i) = lp;
}

__global__ __launch_bounds__(256) void split4_kernel(
    const float* __restrict__ x,  const float* __restrict__ Wq,
    const float* __restrict__ Wk, const float* __restrict__ Wv)
{
    const int z = blockIdx.y;
    const float* src = (z == 0) ? x : (z == 1) ? Wq : (z == 2) ? Wk : Wv;
    __nv_bfloat16* dh = (z == 0) ? g_xh : (z == 1) ? g_Wqh : (z == 2) ? g_Wkh : g_Wvh;
    __nv_bfloat16* dl = (z == 0) ? g_xl : (z == 1) ? g_Wql : (z == 2) ? g_Wkl : g_Wvl;
    split_one(src, dh, dl, (blockIdx.x * 256 + threadIdx.x) * 4);
}

__global__ __launch_bounds__(256) void splitWo_kernel(const float* __restrict__ Wo)
{
    split_one(Wo, g_Woh, g_Wol, (blockIdx.x * 256 + threadIdx.x) * 4);
}

// =================== bf16 split-precision HMMA GEMM ===================
#define KT    32
#define KPAD  40
#define CP_ASYNC16(dst, src) \
    asm volatile("cp.async.cg.shared.global [%0], [%1], 16;" :: "r"(dst), "l"(src))
#define CP_COMMIT() asm volatile("cp.async.commit_group;" ::: "memory")
#define CP_WAIT1()  asm volatile("cp.async.wait_group 1;" ::: "memory")
#define CP_WAIT0()  asm volatile("cp.async.wait_group 0;" ::: "memory")

#define LDSM4(r0, r1, r2, r3, addr) \
    asm volatile("ldmatrix.sync.aligned.m8n8.x4.shared.b16 {%0,%1,%2,%3}, [%4];" \
        : "=r"(r0), "=r"(r1), "=r"(r2), "=r"(r3) : "r"(addr))

__device__ __forceinline__ uint32_t smem_u32(const void* p) {
    uint32_t a;
    asm("{ .reg .u64 t; cvta.to.shared.u64 t, %1; cvt.u32.u64 %0, t; }" : "=r"(a) : "l"(p));
    return a;
}

__device__ __forceinline__ void mma_bf16(float* c, const uint32_t* a, const uint32_t* b)
{
    asm volatile(
        "mma.sync.aligned.m16n8k16.row.col.f32.bf16.bf16.f32 "
        "{%0,%1,%2,%3}, {%4,%5,%6,%7}, {%8,%9}, {%0,%1,%2,%3};"
        : "+f"(c[0]), "+f"(c[1]), "+f"(c[2]), "+f"(c[3])
        : "r"(a[0]), "r"(a[1]), "r"(a[2]), "r"(a[3]), "r"(b[0]), "r"(b[1]));
}

template<int MROWS>
__device__ __forceinline__ void tc_prefetch(
    const __nv_bfloat16* __restrict__ Ah, const __nv_bfloat16* __restrict__ Al,
    const __nv_bfloat16* __restrict__ Bh, const __nv_bfloat16* __restrict__ Bl,
    int m0, int n0, int k0, uint32_t sdst, int tid)
{
    const int ARR_A = MROWS * KPAD * 2;
    const int ARR_BB = 128 * KPAD * 2;
#pragma unroll
    for (int i = 0; i < (MROWS * 4) / 256; ++i) {
        int idx = tid + i * 256;
        int row = idx >> 2, ch = idx & 3;
        uint32_t doff = (uint32_t)(row * (KPAD * 2) + ch * 16);
        size_t aoff = (size_t)(m0 + row) * DMODEL + k0 + ch * 8;
        CP_ASYNC16(sdst + doff,          Ah + aoff);
        CP_ASYNC16(sdst + ARR_A + doff,  Al + aoff);
    }
#pragma unroll
    for (int i = 0; i < 2; ++i) {
        int idx = tid + i * 256;
        int row = idx >> 2, ch = idx & 3;
        uint32_t doff = (uint32_t)(row * (KPAD * 2) + ch * 16);
        size_t boff = (size_t)(n0 + row) * DMODEL + k0 + ch * 8;
        CP_ASYNC16(sdst + 2*ARR_A + doff,          Bh + boff);
        CP_ASYNC16(sdst + 2*ARR_A + ARR_BB + doff, Bl + boff);
    }
}

template<int MROWS>   // 128 or 64
__device__ void tc_gemm_body(
    const __nv_bfloat16* __restrict__ Ah, const __nv_bfloat16* __restrict__ Al,
    const __nv_bfloat16* __restrict__ Bh, const __nv_bfloat16* __restrict__ Bl,
    const float* __restrict__ bias, float* __restrict__ Cout)
{
    extern __shared__ char smem[];
    const int MI = MROWS / 32;
    const int ARR_A = MROWS * KPAD * 2;
    const int STG = 2 * ARR_A + 2 * 128 * KPAD * 2;
    const int tid  = threadIdx.x;
    const int wid  = tid >> 5;
    const int lane = tid & 31;
    const int m0 = blockIdx.y * MROWS, n0 = blockIdx.x << 7;
    const int wm = (wid >> 2) * (MROWS / 2);
    const int wn = (wid & 3) * 32;
    const int lrow = lane >> 2;
    const int lk2  = (lane & 3) << 1;
    const uint32_t sb = smem_u32(smem);

    const int a_lane_off = (lane & 15) * KPAD + ((lane >= 16) ? 8 : 0);
    const int b_lane_off = ((lane & 7) + ((lane >= 16) ? 8 : 0)) * KPAD
                         + (((lane & 15) >= 8) ? 8 : 0);

    float acc[MI][4][4];
#pragma unroll
    for (int i = 0; i < MI; ++i)
#pragma unroll
        for (int j = 0; j < 4; ++j)
#pragma unroll
            for (int e = 0; e < 4; ++e) acc[i][j][e] = 0.f;

    tc_prefetch<MROWS>(Ah, Al, Bh, Bl, m0, n0, 0, sb, tid);
    CP_COMMIT();

    const int NKT = DMODEL / KT;
    for (int kt = 0; kt < NKT; ++kt) {
        if (kt + 1 < NKT) {
            tc_prefetch<MROWS>(Ah, Al, Bh, Bl, m0, n0, (kt + 1) * KT,
                               sb + ((kt + 1) & 1) * STG, tid);
            CP_COMMIT();
            CP_WAIT1();
        } else {
            CP_WAIT0();
        }
        __syncthreads();

        const uint32_t sAh32 = sb + (kt & 1) * STG;
        const uint32_t sAl32 = sAh32 + (uint32_t)(MROWS * KPAD * 2);
        const uint32_t sBh32 = sAh32 + (uint32_t)(2 * MROWS * KPAD * 2);
        const uint32_t sBl32 = sBh32 + (uint32_t)(128 * KPAD * 2);

#pragma unroll
        for (int kk = 0; kk < KT; kk += 16) {
            uint32_t ah[MI][4], al[MI][4], bh[4][2], bl[4][2];
#pragma unroll
            for (int mt = 0; mt < MI; ++mt) {
                uint32_t off = (uint32_t)(((wm + mt * 16) * KPAD + kk + a_lane_off) * 2);
                LDSM4(ah[mt][0], ah[mt][1], ah[mt][2], ah[mt][3], sAh32 + off);
                LDSM4(al[mt][0], al[mt][1], al[mt][2], al[mt][3], sAl32 + off);
            }
#pragma unroll
            for (int np = 0; np < 2; ++np) {
                uint32_t off = (uint32_t)(((wn + np * 16) * KPAD + kk + b_lane_off) * 2);
                LDSM4(bh[2*np][0], bh[2*np][1], bh[2*np+1][0], bh[2*np+1][1], sBh32 + off);
                LDSM4(bl[2*np][0], bl[2*np][1], bl[2*np+1][0], bl[2*np+1][1], sBl32 + off);
            }
#pragma unroll
            for (int mt = 0; mt < MI; ++mt)
#pragma unroll
                for (int nt = 0; nt < 4; ++nt) {
                    mma_bf16(acc[mt][nt], ah[mt], bh[nt]);
                    mma_bf16(acc[mt][nt], ah[mt], bl[nt]);
                    mma_bf16(acc[mt][nt], al[mt], bh[nt]);
                }
        }
        __syncthreads();
    }

#pragma unroll
    for (int mt = 0; mt < MI; ++mt) {
#pragma unroll
        for (int nt = 0; nt < 4; ++nt) {
            int r  = m0 + wm + mt * 16 + lrow;
            int cc = n0 + wn + nt * 8 + lk2;
            float2 bz = *(const float2*)&bias[cc];
            float2 v0 = make_float2(acc[mt][nt][0] + bz.x, acc[mt][nt][1] + bz.y);
            float2 v1 = make_float2(acc[mt][nt][2] + bz.x, acc[mt][nt][3] + bz.y);
            *(float2*)&Cout[(size_t)r * DMODEL + cc]       = v0;
            *(float2*)&Cout[(size_t)(r + 8) * DMODEL + cc] = v1;
        }
    }
}

#define GSMEM128 (2 * (4 * 128 * KPAD * 2))
#define GSMEM64  (2 * (2 * 64 * KPAD * 2 + 2 * 128 * KPAD * 2))

__global__ __launch_bounds__(256, 2)
void tc_gemm_kv_kernel(const float* __restrict__ bk, const float* __restrict__ bv)
{
    int z = blockIdx.z;
    const __nv_bfloat16* Bh = (z == 0) ? g_Wkh : g_Wvh;
    const __nv_bfloat16* Bl = (z == 0) ? g_Wkl : g_Wvl;
    const float* b = (z == 0) ? bk : bv;
    float* out = (z == 0) ? g_K : g_V;
    tc_gemm_body<128>(g_xh, g_xl, Bh, Bl, b, out);
}

__global__ __launch_bounds__(256, 2)
void tc_gemm_q_kernel(const float* __restrict__ bq)
{
    tc_gemm_body<128>(g_xh, g_xl, g_Wqh, g_Wql, bq, g_Q);
}

__global__ __launch_bounds__(256, 2)
void tc_gemm_o_kernel(const float* __restrict__ bo, float* __restrict__ out)
{
    tc_gemm_body<64>(g_Oh, g_Ol, g_Woh, g_Wol, bo, out);
}

// ======================= fused cw + exp + chunksum =======================
struct ChunkSmem {
    float qcsT[DHEAD][SP];  // [d][c]
    float KsT[DHEAD][SP];   // [d][t]
    float Ks[CHUNK][SP];    // [t][d]
    float Vs[CHUNK][SP];    // [t][d]
    float cwsT[CHUNK][SP];  // [t][c]  (exp'd)
};

__global__ __launch_bounds__(256) void chunksum_kernel(const float* __restrict__ q_c)
{
    extern __shared__ char smem_raw[];
    ChunkSmem& sm = *(ChunkSmem*)smem_raw;
    const int h = blockIdx.y, ch = blockIdx.x;
    const int s0 = ch * CHUNK;
    const int tid = threadIdx.x;
    const int tx = tid & 15, ty = tid >> 4;

    for (int e = tid; e < NC * CHUNK; e += 256) {
        int r = e >> 6, d = e & 63;
        sm.qcsT[d][r] = q_c[(size_t)r * DMODEL + h * DHEAD + d];
        float kv = g_K[(size_t)(s0 + r) * DMODEL + h * DHEAD + d];
        sm.KsT[d][r] = kv;
        sm.Ks[r][d]  = kv;
        sm.Vs[r][d]  = g_V[(size_t)(s0 + r) * DMODEL + h * DHEAD + d];
    }
    __syncthreads();

    // cw[c][t] = exp( qc[c,:].K[t,:] )
    {
        float acc[4][4];
#pragma unroll
        for (int i = 0; i < 4; ++i)
#pragma unroll
            for (int j = 0; j < 4; ++j) acc[i][j] = 0.f;
#pragma unroll 4
        for (int d = 0; d < DHEAD; ++d) {
            float4 a4 = *(const float4*)&sm.qcsT[d][ty << 2];
            float4 b4 = *(const float4*)&sm.KsT[d][tx << 2];
            float ar[4] = {a4.x, a4.y, a4.z, a4.w};
            float br[4] = {b4.x, b4.y, b4.z, b4.w};
#pragma unroll
            for (int i = 0; i < 4; ++i)
#pragma unroll
                for (int j = 0; j < 4; ++j) acc[i][j] = fmaf(ar[i], br[j], acc[i][j]);
        }
#pragma unroll
        for (int i = 0; i < 4; ++i) {
            int c = (ty << 2) + i;
#pragma unroll
            for (int j = 0; j < 4; ++j) {
                int t = (tx << 2) + j;
                float v = expf(acc[i][j]);
                sm.cwsT[t][c] = v;
                g_cw[((size_t)h * NC + c) * SLEN + s0 + t] = v;
            }
        }
    }
    __syncthreads();

    float ak[4][4], av[4][4];
#pragma unroll
    for (int i = 0; i < 4; ++i)
#pragma unroll
        for (int j = 0; j < 4; ++j) { ak[i][j] = 0.f; av[i][j] = 0.f; }

#pragma unroll 4
    for (int t = 0; t < CHUNK; ++t) {
        float4 a4 = *(const float4*)&sm.cwsT[t][ty << 2];
        float4 k4 = *(const float4*)&sm.Ks[t][tx << 2];
        float4 v4 = *(const float4*)&sm.Vs[t][tx << 2];
        float ar[4] = {a4.x, a4.y, a4.z, a4.w};
        float bk[4] = {k4.x, k4.y, k4.z, k4.w};
        float bv[4] = {v4.x, v4.y, v4.z, v4.w};
#pragma unroll
        for (int i = 0; i < 4; ++i)
#pragma unroll
            for (int j = 0; j < 4; ++j) {
                ak[i][j] = fmaf(ar[i], bk[j], ak[i][j]);
                av[i][j] = fmaf(ar[i], bv[j], av[i][j]);
            }
    }
    const size_t base = ((size_t)(h * NCHUNK + ch) * NC) * DHEAD;
#pragma unroll
    for (int i = 0; i < 4; ++i) {
        int c = (ty << 2) + i;
#pragma unroll
        for (int j = 0; j < 4; ++j) {
            int d = (tx << 2) + j;
            g_Tk[base + (size_t)c * DHEAD + d] = ak[i][j];
            g_Tv[base + (size_t)c * DHEAD + d] = av[i][j];
        }
    }
    if (tid < NC) {
        float s = 0.f;
#pragma unroll
        for (int t = 0; t < CHUNK; ++t) s += sm.cwsT[t][tid];
        g_Tn[(size_t)(h * NCHUNK + ch) * NC + tid] = s;
    }
}

// ---------------- parallel exclusive prefix over chunks ----------------
__global__ __launch_bounds__(256) void prefix_kernel()
{
    const int gid = blockIdx.x * 256 + threadIdx.x;
    if (blockIdx.x < 256) {
        const int h = gid >> 12;
        const int e = gid & 4095;
        const size_t base0 = ((size_t)h * NCHUNK * NC) * DHEAD + e;
        const size_t cstep = (size_t)NC * DHEAD;
        float tk[NCHUNK], tv[NCHUNK];
#pragma unroll
        for (int ch = 0; ch < NCHUNK; ++ch) {
            tk[ch] = g_Tk[base0 + ch * cstep];
            tv[ch] = g_Tv[base0 + ch * cstep];
        }
        float rk = 0.f, rv = 0.f;
#pragma unroll
        for (int ch = 0; ch < NCHUNK; ++ch) {
            g_A0k[base0 + ch * cstep] = rk; rk += tk[ch];
            g_A0v[base0 + ch * cstep] = rv; rv += tv[ch];
        }
    } else {
        const int e = (blockIdx.x - 256) * 256 + threadIdx.x;  // h*NC + c
        const int h = e >> 6;
        const int c = e & 63;
        const size_t base0 = (size_t)h * NCHUNK * NC + c;
        float tn[NCHUNK];
#pragma unroll
        for (int ch = 0; ch < NCHUNK; ++ch) tn[ch] = g_Tn[base0 + ch * NC];
        float rn = 0.f;
#pragma unroll
        for (int ch = 0; ch < NCHUNK; ++ch) { g_N0[base0 + ch * NC] = rn; rn += tn[ch]; }
    }
}

// ---------------- per-(head,chunk) attention (vectorized) --------------
struct K7Smem {
    float QsT[DHEAD][SP];   // [d][s]  (pre-scaled)
    float KsT[DHEAD][SP];   // [d][t]
    float Vs[CHUNK][SP];    // [t][d]
    float cwsN[NC][SP];     // [c][t]
    float cwsT[CHUNK][SP];  // [t][c]
    float ncs[NC][SP];      // [c][s]
    float A0kT[DHEAD][SP];  // [d][c]
    float A0v[NC][SP];      // [c][d]
    float GT[CHUNK][SP];    // [t][s]
    float PT[NC][SP];       // [c][s]
    float n0v[NC];
};

__global__ __launch_bounds__(256) void attn_kernel(const float* __restrict__ beta)
{
    extern __shared__ char smem_raw[];
    K7Smem& sm = *(K7Smem*)smem_raw;
    const int h = blockIdx.y, ch = blockIdx.x;
    const int s0 = ch * CHUNK;
    const int tid = threadIdx.x;
    const int tx = tid & 15, ty = tid >> 4;
    const float qscale = 0.125f * expf(-beta[h]);

    const size_t abase = ((size_t)(h * NCHUNK + ch) * NC) * DHEAD;
    for (int e = tid; e < CHUNK * DHEAD; e += 256) {
        int r = e >> 6, d = e & 63;
        sm.QsT[d][r] = g_Q[(size_t)(s0 + r) * DMODEL + h * DHEAD + d] * qscale;
        sm.KsT[d][r] = g_K[(size_t)(s0 + r) * DMODEL + h * DHEAD + d];
        sm.Vs[r][d]  = g_V[(size_t)(s0 + r) * DMODEL + h * DHEAD + d];
        float cv = g_cw[((size_t)h * NC + r) * SLEN + s0 + d];
        sm.cwsN[r][d] = cv;
        sm.cwsT[d][r] = cv;
        sm.A0kT[d][r] = g_A0k[abase + e];
        sm.A0v[r][d]  = g_A0v[abase + e];
    }
    if (tid < NC) sm.n0v[tid] = g_N0[(size_t)(h * NCHUNK + ch) * NC + tid];
    __syncthreads();

    if (tid < NC) {
        float run = sm.n0v[tid];
#pragma unroll
        for (int t = 0; t < CHUNK; ++t) { run += sm.cwsN[tid][t]; sm.ncs[tid][t] = run; }
    }

    // G[t][s] = (t<=s) ? Qs[s].Ks[t] : 0
    {
        float acc[4][4];
#pragma unroll
        for (int i = 0; i < 4; ++i)
#pragma unroll
            for (int j = 0; j < 4; ++j) acc[i][j] = 0.f;
#pragma unroll 4
        for (int d = 0; d < DHEAD; ++d) {
            float4 a4 = *(const float4*)&sm.QsT[d][ty << 2];
            float4 b4 = *(const float4*)&sm.KsT[d][tx << 2];
            float ar[4] = {a4.x, a4.y, a4.z, a4.w};
            float br[4] = {b4.x, b4.y, b4.z, b4.w};
#pragma unroll
            for (int i = 0; i < 4; ++i)
#pragma unroll
                for (int j = 0; j < 4; ++j) acc[i][j] = fmaf(ar[i], br[j], acc[i][j]);
        }
#pragma unroll
        for (int i = 0; i < 4; ++i) {
            int s = (ty << 2) + i;
#pragma unroll
            for (int j = 0; j < 4; ++j) {
                int t = (tx << 2) + j;
                sm.GT[t][s] = (t <= s) ? acc[i][j] : 0.f;
            }
        }
    }
    __syncthreads();

    // P[c][s] = (Qs[s].A0k[c] + sum_t G[t][s]*cwT[t][c]) / ncs[c][s]
    {
        float acc[4][4];
#pragma unroll
        for (int i = 0; i < 4; ++i)
#pragma unroll
            for (int j = 0; j < 4; ++j) acc[i][j] = 0.f;
#pragma unroll 4
        for (int d = 0; d < DHEAD; ++d) {
            float4 a4 = *(const float4*)&sm.QsT[d][ty << 2];
            float4 b4 = *(const float4*)&sm.A0kT[d][tx << 2];
            float ar[4] = {a4.x, a4.y, a4.z, a4.w};
            float br[4] = {b4.x, b4.y, b4.z, b4.w};
#pragma unroll
            for (int i = 0; i < 4; ++i)
#pragma unroll
                for (int j = 0; j < 4; ++j) acc[i][j] = fmaf(ar[i], br[j], acc[i][j]);
        }
#pragma unroll 4
        for (int t = 0; t < CHUNK; ++t) {
            float4 a4 = *(const float4*)&sm.GT[t][ty << 2];
            float4 b4 = *(const float4*)&sm.cwsT[t][tx << 2];
            float ar[4] = {a4.x, a4.y, a4.z, a4.w};
            float br[4] = {b4.x, b4.y, b4.z, b4.w};
#pragma unroll
            for (int i = 0; i < 4; ++i)
#pragma unroll
                for (int j = 0; j < 4; ++j) acc[i][j] = fmaf(ar[i], br[j], acc[i][j]);
        }
#pragma unroll
        for (int i = 0; i < 4; ++i) {
            int s = (ty << 2) + i;
#pragma unroll
            for (int j = 0; j < 4; ++j) {
                int c = (tx << 2) + j;
                sm.PT[c][s] = acc[i][j] / sm.ncs[c][s];
            }
        }
    }
    __syncthreads();

    // softmax over c per s, then /ncs
    if (tid < CHUNK) {
        int s = tid;
        float m = -INFINITY;
#pragma unroll
        for (int c = 0; c < NC; ++c) m = fmaxf(m, sm.PT[c][s]);
        float sum = 0.f;
#pragma unroll
        for (int c = 0; c < NC; ++c) { float e = expf(sm.PT[c][s] - m); sm.PT[c][s] = e; sum += e; }
        float inv = 1.f / sum;
#pragma unroll
        for (int c = 0; c < NC; ++c) sm.PT[c][s] = sm.PT[c][s] * inv / sm.ncs[c][s];
    }
    __syncthreads();

    // W[t][s] = (t<=s) ? sum_c P[c][s]*cwN[c][t] : 0   (into GT)
    {
        float acc[4][4];
#pragma unroll
        for (int i = 0; i < 4; ++i)
#pragma unroll
            for (int j = 0; j < 4; ++j) acc[i][j] = 0.f;
#pragma unroll 4
        for (int c = 0; c < NC; ++c) {
            float4 a4 = *(const float4*)&sm.PT[c][ty << 2];
            float4 b4 = *(const float4*)&sm.cwsN[c][tx << 2];
            float ar[4] = {a4.x, a4.y, a4.z, a4.w};
            float br[4] = {b4.x, b4.y, b4.z, b4.w};
#pragma unroll
            for (int i = 0; i < 4; ++i)
#pragma unroll
                for (int j = 0; j < 4; ++j) acc[i][j] = fmaf(ar[i], br[j], acc[i][j]);
        }
        __syncthreads();
#pragma unroll
        for (int i = 0; i < 4; ++i) {
            int s = (ty << 2) + i;
#pragma unroll
            for (int j = 0; j < 4; ++j) {
                int t = (tx << 2) + j;
                sm.GT[t][s] = (t <= s) ? acc[i][j] : 0.f;
            }
        }
    }
    __syncthreads();

    // O[s][d] = sum_t W[t][s]*V[t][d] + sum_c P[c][s]*A0v[c][d]
    {
        float acc[4][4];
#pragma unroll
        for (int i = 0; i < 4; ++i)
#pragma unroll
            for (int j = 0; j < 4; ++j) acc[i][j] = 0.f;
#pragma unroll 4
        for (int t = 0; t < CHUNK; ++t) {
            float4 a4 = *(const float4*)&sm.GT[t][ty << 2];
            float4 b4 = *(const float4*)&sm.Vs[t][tx << 2];
            float ar[4] = {a4.x, a4.y, a4.z, a4.w};
            float br[4] = {b4.x, b4.y, b4.z, b4.w};
#pragma unroll
            for (int i = 0; i < 4; ++i)
#pragma unroll
                for (int j = 0; j < 4; ++j) acc[i][j] = fmaf(ar[i], br[j], acc[i][j]);
        }
#pragma unroll 4
        for (int c = 0; c < NC; ++c) {
            float4 a4 = *(const float4*)&sm.PT[c][ty << 2];
            float4 b4 = *(const float4*)&sm.A0v[c][tx << 2];
            float ar[4] = {a4.x, a4.y, a4.z, a4.w};
            float br[4] = {b4.x, b4.y, b4.z, b4.w};
#pragma unroll
            for (int i = 0; i < 4; ++i)
#pragma unroll
                for (int j = 0; j < 4; ++j) acc[i][j] = fmaf(ar[i], br[j], acc[i][j]);
        }
        // write O directly as bf16 hi/lo pairs for the Wo GEMM
#pragma unroll
        for (int i = 0; i < 4; ++i) {
            int s = (ty << 2) + i;
            size_t rowoff = (size_t)(s0 + s) * DMODEL + h * DHEAD + (tx << 2);
            __nv_bfloat16 h0 = __float2bfloat16_rn(acc[i][0]);
            __nv_bfloat16 h1 = __float2bfloat16_rn(acc[i][1]);
            __nv_bfloat16 h2 = __float2bfloat16_rn(acc[i][2]);
            __nv_bfloat16 h3 = __float2bfloat16_rn(acc[i][3]);
            *(uint32_t*)&g_Oh[rowoff]     = pack_bf2(h0, h1);
            *(uint32_t*)&g_Oh[rowoff + 2] = pack_bf2(h2, h3);
            *(uint32_t*)&g_Ol[rowoff] =
                pack_bf2(__float2bfloat16_rn(acc[i][0] - __bfloat162float(h0)),
                         __float2bfloat16_rn(acc[i][1] - __bfloat162float(h1)));
            *(uint32_t*)&g_Ol[rowoff + 2] =
                pack_bf2(__float2bfloat16_rn(acc[i][2] - __bfloat162float(h2)),
                         __float2bfloat16_rn(acc[i][3] - __bfloat162float(h3)));
        }
    }
}

// ---------------- launch -----------------------------------------------
extern "C" void kernel_launch(void* const* d_in, const int* in_sizes, int n_in,
                              void* d_out, int out_size)
{
    const float* x    = (const float*)d_in[0];
    const float* q_c  = (const float*)d_in[1];
    const float* beta = (const float*)d_in[2];
    const float* Wq   = (const float*)d_in[3];
    const float* bq   = (const float*)d_in[4];
    const float* Wk   = (const float*)d_in[5];
    const float* bk   = (const float*)d_in[6];
    const float* Wv   = (const float*)d_in[7];
    const float* bv   = (const float*)d_in[8];
    const float* Wo   = (const float*)d_in[9];
    const float* bo   = (const float*)d_in[10];
    float* out = (float*)d_out;

    static bool inited = false;
    static cudaStream_t s2;
    static cudaEvent_t evFork, evQ, evWo;
    if (!inited) {
        cudaFuncSetAttribute(attn_kernel, cudaFuncAttributeMaxDynamicSharedMemorySize,
                             (int)sizeof(K7Smem));
        cudaFuncSetAttribute(chunksum_kernel, cudaFuncAttributeMaxDynamicSharedMemorySize,
                             (int)sizeof(ChunkSmem));
        cudaFuncSetAttribute(tc_gemm_kv_kernel, cudaFuncAttributeMaxDynamicSharedMemorySize, GSMEM128);
        cudaFuncSetAttribute(tc_gemm_q_kernel, cudaFuncAttributeMaxDynamicSharedMemorySize, GSMEM128);
        cudaFuncSetAttribute(tc_gemm_o_kernel, cudaFuncAttributeMaxDynamicSharedMemorySize, GSMEM64);
        cudaStreamCreateWithFlags(&s2, cudaStreamNonBlocking);
        cudaEventCreateWithFlags(&evFork, cudaEventDisableTiming);
        cudaEventCreateWithFlags(&evQ, cudaEventDisableTiming);
        cudaEventCreateWithFlags(&evWo, cudaEventDisableTiming);
        inited = true;
    }

    // main stream: split (x, Wq, Wk, Wv) then KV GEMM  (R12 topology)
    split4_kernel<<<dim3(1024, 4), 256>>>(x, Wq, Wk, Wv);
    tc_gemm_kv_kernel<<<dim3(8, 8, 2), 256, GSMEM128>>>(bk, bv);

    // fork AFTER the KV GEMM: Q GEMM overlaps chunksum/prefix (complementary pipes)
    cudaEventRecord(evFork, 0);
    cudaStreamWaitEvent(s2, evFork, 0);
    tc_gemm_q_kernel<<<dim3(8, 8), 256, GSMEM128, s2>>>(bq);
    cudaEventRecord(evQ, s2);            // attn gate: Q only
    splitWo_kernel<<<1024, 256, 0, s2>>>(Wo);
    cudaEventRecord(evWo, s2);           // Wo-GEMM gate: covered by attn runtime

    // main stream: chunksum + prefix (depend on K,V only)
    chunksum_kernel<<<dim3(NCHUNK, NHEAD), 256, sizeof(ChunkSmem)>>>(q_c);
    prefix_kernel<<<260, 256>>>();

    // join: attn needs Q + prefix (NOT the Wo split)
    cudaStreamWaitEvent(0, evQ, 0);
    attn_kernel<<<dim3(NCHUNK, NHEAD), 256, sizeof(K7Smem)>>>(beta);
    cudaStreamWaitEvent(0, evWo, 0);
    tc_gemm_o_kernel<<<dim3(8, 16), 256, GSMEM64>>>(bo, out);
}

// round 16
// speedup vs baseline: 1.1042x; 1.0391x over previous
#include <cuda_runtime.h>
#include <cuda_bf16.h>
#include <math.h>
#include <stdint.h>

#define SLEN   1024
#define DMODEL 1024
#define NHEAD  16
#define DHEAD  64
#define NC     64
#define CHUNK  64
#define NCHUNK 16
#define SP     68      // smem row stride (floats): 272B, 16B-aligned

// ---------------- global scratch ----------------
__device__ float g_Q[SLEN*DMODEL];
__device__ float g_K[SLEN*DMODEL];
__device__ float g_V[SLEN*DMODEL];
__device__ float g_cw[NHEAD*NC*SLEN];
__device__ float g_Tk[NHEAD*NCHUNK*NC*DHEAD];
__device__ float g_Tv[NHEAD*NCHUNK*NC*DHEAD];
__device__ float g_Tn[NHEAD*NCHUNK*NC];
__device__ float g_A0k[NHEAD*NCHUNK*NC*DHEAD];
__device__ float g_A0v[NHEAD*NCHUNK*NC*DHEAD];
__device__ float g_N0[NHEAD*NCHUNK*NC];

// bf16 hi/lo split buffers
__device__ __nv_bfloat16 g_xh[SLEN*DMODEL],  g_xl[SLEN*DMODEL];
__device__ __nv_bfloat16 g_Wqh[DMODEL*DMODEL], g_Wql[DMODEL*DMODEL];
__device__ __nv_bfloat16 g_Wkh[DMODEL*DMODEL], g_Wkl[DMODEL*DMODEL];
__device__ __nv_bfloat16 g_Wvh[DMODEL*DMODEL], g_Wvl[DMODEL*DMODEL];
__device__ __nv_bfloat16 g_Woh[DMODEL*DMODEL], g_Wol[DMODEL*DMODEL];
__device__ __nv_bfloat16 g_Oh[SLEN*DMODEL],  g_Ol[SLEN*DMODEL];

__device__ __forceinline__ uint32_t pack_bf2(__nv_bfloat16 a, __nv_bfloat16 b) {
    return (uint32_t)__bfloat16_as_ushort(a) | ((uint32_t)__bfloat16_as_ushort(b) << 16);
}

// ---------------- split fp32 -> bf16 hi/lo ----------------
__device__ __forceinline__ void split_one(const float* __restrict__ src,
                                          __nv_bfloat16* __restrict__ dh,
                                          __nv_bfloat16* __restrict__ dl,
                                          int i)
{
    float4 v = *(const float4*)(src + i);
    __nv_bfloat16 h0 = __float2bfloat16_rn(v.x), h1 = __float2bfloat16_rn(v.y);
    __nv_bfloat16 h2 = __float2bfloat16_rn(v.z), h3 = __float2bfloat16_rn(v.w);
    uint2 hp = make_uint2(pack_bf2(h0, h1), pack_bf2(h2, h3));
    uint2 lp = make_uint2(
        pack_bf2(__float2bfloat16_rn(v.x - __bfloat162float(h0)),
                 __float2bfloat16_rn(v.y - __bfloat162float(h1))),
        pack_bf2(__float2bfloat16_rn(v.z - __bfloat162float(h2)),
                 __float2bfloat16_rn(v.w - __bfloat162float(h3))));
    *(uint2*)(dh + i) = hp;
    *(uint2*)(dl + i) = lp;
}

__global__ __launch_bounds__(256) void split4_kernel(
    const float* __restrict__ x,  const float* __restrict__ Wq,
    const float* __restrict__ Wk, const float* __restrict__ Wv)
{
    const int z = blockIdx.y;
    const float* src = (z == 0) ? x : (z == 1) ? Wq : (z == 2) ? Wk : Wv;
    __nv_bfloat16* dh = (z == 0) ? g_xh : (z == 1) ? g_Wqh : (z == 2) ? g_Wkh : g_Wvh;
    __nv_bfloat16* dl = (z == 0) ? g_xl : (z == 1) ? g_Wql : (z == 2) ? g_Wkl : g_Wvl;
    split_one(src, dh, dl, (blockIdx.x * 256 + threadIdx.x) * 4);
}

__global__ __launch_bounds__(256) void splitWo_kernel(const float* __restrict__ Wo)
{
    split_one(Wo, g_Woh, g_Wol, (blockIdx.x * 256 + threadIdx.x) * 4);
}

// =================== bf16 split-precision HMMA GEMM ===================
#define KT    32
#define KPAD  40
#define CP_ASYNC16(dst, src) \
    asm volatile("cp.async.cg.shared.global [%0], [%1], 16;" :: "r"(dst), "l"(src))
#define CP_COMMIT() asm volatile("cp.async.commit_group;" ::: "memory")
#define CP_WAIT1()  asm volatile("cp.async.wait_group 1;" ::: "memory")
#define CP_WAIT0()  asm volatile("cp.async.wait_group 0;" ::: "memory")

#define LDSM4(r0, r1, r2, r3, addr) \
    asm volatile("ldmatrix.sync.aligned.m8n8.x4.shared.b16 {%0,%1,%2,%3}, [%4];" \
        : "=r"(r0), "=r"(r1), "=r"(r2), "=r"(r3) : "r"(addr))

__device__ __forceinline__ uint32_t smem_u32(const void* p) {
    uint32_t a;
    asm("{ .reg .u64 t; cvta.to.shared.u64 t, %1; cvt.u32.u64 %0, t; }" : "=r"(a) : "l"(p));
    return a;
}

__device__ __forceinline__ void mma_bf16(float* c, const uint32_t* a, const uint32_t* b)
{
    asm volatile(
        "mma.sync.aligned.m16n8k16.row.col.f32.bf16.bf16.f32 "
        "{%0,%1,%2,%3}, {%4,%5,%6,%7}, {%8,%9}, {%0,%1,%2,%3};"
        : "+f"(c[0]), "+f"(c[1]), "+f"(c[2]), "+f"(c[3])
        : "r"(a[0]), "r"(a[1]), "r"(a[2]), "r"(a[3]), "r"(b[0]), "r"(b[1]));
}

template<int MROWS>
__device__ __forceinline__ void tc_prefetch(
    const __nv_bfloat16* __restrict__ Ah, const __nv_bfloat16* __restrict__ Al,
    const __nv_bfloat16* __restrict__ Bh, const __nv_bfloat16* __restrict__ Bl,
    int m0, int n0, int k0, uint32_t sdst, int tid)
{
    const int ARR_A = MROWS * KPAD * 2;
    const int ARR_BB = 128 * KPAD * 2;
#pragma unroll
    for (int i = 0; i < (MROWS * 4) / 256; ++i) {
        int idx = tid + i * 256;
        int row = idx >> 2, ch = idx & 3;
        uint32_t doff = (uint32_t)(row * (KPAD * 2) + ch * 16);
        size_t aoff = (size_t)(m0 + row) * DMODEL + k0 + ch * 8;
        CP_ASYNC16(sdst + doff,          Ah + aoff);
        CP_ASYNC16(sdst + ARR_A + doff,  Al + aoff);
    }
#pragma unroll
    for (int i = 0; i < 2; ++i) {
        int idx = tid + i * 256;
        int row = idx >> 2, ch = idx & 3;
        uint32_t doff = (uint32_t)(row * (KPAD * 2) + ch * 16);
        size_t boff = (size_t)(n0 + row) * DMODEL + k0 + ch * 8;
        CP_ASYNC16(sdst + 2*ARR_A + doff,          Bh + boff);
        CP_ASYNC16(sdst + 2*ARR_A + ARR_BB + doff, Bl + boff);
    }
}

template<int MROWS>   // 128 or 64
__device__ void tc_gemm_body(
    const __nv_bfloat16* __restrict__ Ah, const __nv_bfloat16* __restrict__ Al,
    const __nv_bfloat16* __restrict__ Bh, const __nv_bfloat16* __restrict__ Bl,
    const float* __restrict__ bias, float* __restrict__ Cout)
{
    extern __shared__ char smem[];
    const int MI = MROWS / 32;
    const int ARR_A = MROWS * KPAD * 2;
    const int STG = 2 * ARR_A + 2 * 128 * KPAD * 2;
    const int tid  = threadIdx.x;
    const int wid  = tid >> 5;
    const int lane = tid & 31;
    const int m0 = blockIdx.y * MROWS, n0 = blockIdx.x << 7;
    const int wm = (wid >> 2) * (MROWS / 2);
    const int wn = (wid & 3) * 32;
    const int lrow = lane >> 2;
    const int lk2  = (lane & 3) << 1;
    const uint32_t sb = smem_u32(smem);

    const int a_lane_off = (lane & 15) * KPAD + ((lane >= 16) ? 8 : 0);
    const int b_lane_off = ((lane & 7) + ((lane >= 16) ? 8 : 0)) * KPAD
                         + (((lane & 15) >= 8) ? 8 : 0);

    float acc[MI][4][4];
#pragma unroll
    for (int i = 0; i < MI; ++i)
#pragma unroll
        for (int j = 0; j < 4; ++j)
#pragma unroll
            for (int e = 0; e < 4; ++e) acc[i][j][e] = 0.f;

    tc_prefetch<MROWS>(Ah, Al, Bh, Bl, m0, n0, 0, sb, tid);
    CP_COMMIT();

    const int NKT = DMODEL / KT;
    for (int kt = 0; kt < NKT; ++kt) {
        if (kt + 1 < NKT) {
            tc_prefetch<MROWS>(Ah, Al, Bh, Bl, m0, n0, (kt + 1) * KT,
                               sb + ((kt + 1) & 1) * STG, tid);
            CP_COMMIT();
            CP_WAIT1();
        } else {
            CP_WAIT0();
        }
        __syncthreads();

        const uint32_t sAh32 = sb + (kt & 1) * STG;
        const uint32_t sAl32 = sAh32 + (uint32_t)(MROWS * KPAD * 2);
        const uint32_t sBh32 = sAh32 + (uint32_t)(2 * MROWS * KPAD * 2);
        const uint32_t sBl32 = sBh32 + (uint32_t)(128 * KPAD * 2);

#pragma unroll
        for (int kk = 0; kk < KT; kk += 16) {
            uint32_t ah[MI][4], al[MI][4], bh[4][2], bl[4][2];
#pragma unroll
            for (int mt = 0; mt < MI; ++mt) {
                uint32_t off = (uint32_t)(((wm + mt * 16) * KPAD + kk + a_lane_off) * 2);
                LDSM4(ah[mt][0], ah[mt][1], ah[mt][2], ah[mt][3], sAh32 + off);
                LDSM4(al[mt][0], al[mt][1], al[mt][2], al[mt][3], sAl32 + off);
            }
#pragma unroll
            for (int np = 0; np < 2; ++np) {
                uint32_t off = (uint32_t)(((wn + np * 16) * KPAD + kk + b_lane_off) * 2);
                LDSM4(bh[2*np][0], bh[2*np][1], bh[2*np+1][0], bh[2*np+1][1], sBh32 + off);
                LDSM4(bl[2*np][0], bl[2*np][1], bl[2*np+1][0], bl[2*np+1][1], sBl32 + off);
            }
#pragma unroll
            for (int mt = 0; mt < MI; ++mt)
#pragma unroll
                for (int nt = 0; nt < 4; ++nt) {
                    mma_bf16(acc[mt][nt], ah[mt], bh[nt]);
                    mma_bf16(acc[mt][nt], ah[mt], bl[nt]);
                    mma_bf16(acc[mt][nt], al[mt], bh[nt]);
                }
        }
        __syncthreads();
    }

#pragma unroll
    for (int mt = 0; mt < MI; ++mt) {
#pragma unroll
        for (int nt = 0; nt < 4; ++nt) {
            int r  = m0 + wm + mt * 16 + lrow;
            int cc = n0 + wn + nt * 8 + lk2;
            float2 bz = *(const float2*)&bias[cc];
            float2 v0 = make_float2(acc[mt][nt][0] + bz.x, acc[mt][nt][1] + bz.y);
            float2 v1 = make_float2(acc[mt][nt][2] + bz.x, acc[mt][nt][3] + bz.y);
            *(float2*)&Cout[(size_t)r * DMODEL + cc]       = v0;
            *(float2*)&Cout[(size_t)(r + 8) * DMODEL + cc] = v1;
        }
    }
}

#define GSMEM128 (2 * (4 * 128 * KPAD * 2))
#define GSMEM64  (2 * (2 * 64 * KPAD * 2 + 2 * 128 * KPAD * 2))

__global__ __launch_bounds__(256, 2)
void tc_gemm_kv_kernel(const float* __restrict__ bk, const float* __restrict__ bv)
{
    int z = blockIdx.z;
    const __nv_bfloat16* Bh = (z == 0) ? g_Wkh : g_Wvh;
    const __nv_bfloat16* Bl = (z == 0) ? g_Wkl : g_Wvl;
    const float* b = (z == 0) ? bk : bv;
    float* out = (z == 0) ? g_K : g_V;
    tc_gemm_body<128>(g_xh, g_xl, Bh, Bl, b, out);
}

__global__ __launch_bounds__(256, 2)
void tc_gemm_q_kernel(const float* __restrict__ bq)
{
    tc_gemm_body<128>(g_xh, g_xl, g_Wqh, g_Wql, bq, g_Q);
}

__global__ __launch_bounds__(256, 2)
void tc_gemm_o_kernel(const float* __restrict__ bo, float* __restrict__ out)
{
    tc_gemm_body<64>(g_Oh, g_Ol, g_Woh, g_Wol, bo, out);
}

// ======================= fused cw + exp + chunksum =======================
struct ChunkSmem {
    float qcsT[DHEAD][SP];  // [d][c]
    float KsT[DHEAD][SP];   // [d][t]
    float Ks[CHUNK][SP];    // [t][d]
    float Vs[CHUNK][SP];    // [t][d]
    float cwsT[CHUNK][SP];  // [t][c]  (exp'd)
};

__global__ __launch_bounds__(256) void chunksum_kernel(const float* __restrict__ q_c)
{
    extern __shared__ char smem_raw[];
    ChunkSmem& sm = *(ChunkSmem*)smem_raw;
    const int h = blockIdx.y, ch = blockIdx.x;
    const int s0 = ch * CHUNK;
    const int tid = threadIdx.x;
    const int tx = tid & 15, ty = tid >> 4;

    for (int e = tid; e < NC * CHUNK; e += 256) {
        int r = e >> 6, d = e & 63;
        sm.qcsT[d][r] = q_c[(size_t)r * DMODEL + h * DHEAD + d];
        float kv = g_K[(size_t)(s0 + r) * DMODEL + h * DHEAD + d];
        sm.KsT[d][r] = kv;
        sm.Ks[r][d]  = kv;
        sm.Vs[r][d]  = g_V[(size_t)(s0 + r) * DMODEL + h * DHEAD + d];
    }
    __syncthreads();

    {
        float acc[4][4];
#pragma unroll
        for (int i = 0; i < 4; ++i)
#pragma unroll
            for (int j = 0; j < 4; ++j) acc[i][j] = 0.f;
#pragma unroll 4
        for (int d = 0; d < DHEAD; ++d) {
            float4 a4 = *(const float4*)&sm.qcsT[d][ty << 2];
            float4 b4 = *(const float4*)&sm.KsT[d][tx << 2];
            float ar[4] = {a4.x, a4.y, a4.z, a4.w};
            float br[4] = {b4.x, b4.y, b4.z, b4.w};
#pragma unroll
            for (int i = 0; i < 4; ++i)
#pragma unroll
                for (int j = 0; j < 4; ++j) acc[i][j] = fmaf(ar[i], br[j], acc[i][j]);
        }
#pragma unroll
        for (int i = 0; i < 4; ++i) {
            int c = (ty << 2) + i;
#pragma unroll
            for (int j = 0; j < 4; ++j) {
                int t = (tx << 2) + j;
                float v = expf(acc[i][j]);
                sm.cwsT[t][c] = v;
                g_cw[((size_t)h * NC + c) * SLEN + s0 + t] = v;
            }
        }
    }
    __syncthreads();

    float ak[4][4], av[4][4];
#pragma unroll
    for (int i = 0; i < 4; ++i)
#pragma unroll
        for (int j = 0; j < 4; ++j) { ak[i][j] = 0.f; av[i][j] = 0.f; }

#pragma unroll 4
    for (int t = 0; t < CHUNK; ++t) {
        float4 a4 = *(const float4*)&sm.cwsT[t][ty << 2];
        float4 k4 = *(const float4*)&sm.Ks[t][tx << 2];
        float4 v4 = *(const float4*)&sm.Vs[t][tx << 2];
        float ar[4] = {a4.x, a4.y, a4.z, a4.w};
        float bk[4] = {k4.x, k4.y, k4.z, k4.w};
        float bv[4] = {v4.x, v4.y, v4.z, v4.w};
#pragma unroll
        for (int i = 0; i < 4; ++i)
#pragma unroll
            for (int j = 0; j < 4; ++j) {
                ak[i][j] = fmaf(ar[i], bk[j], ak[i][j]);
                av[i][j] = fmaf(ar[i], bv[j], av[i][j]);
            }
    }
    const size_t base = ((size_t)(h * NCHUNK + ch) * NC) * DHEAD;
#pragma unroll
    for (int i = 0; i < 4; ++i) {
        int c = (ty << 2) + i;
#pragma unroll
        for (int j = 0; j < 4; ++j) {
            int d = (tx << 2) + j;
            g_Tk[base + (size_t)c * DHEAD + d] = ak[i][j];
            g_Tv[base + (size_t)c * DHEAD + d] = av[i][j];
        }
    }
    if (tid < NC) {
        float s = 0.f;
#pragma unroll
        for (int t = 0; t < CHUNK; ++t) s += sm.cwsT[t][tid];
        g_Tn[(size_t)(h * NCHUNK + ch) * NC + tid] = s;
    }
}

// ---------------- parallel exclusive prefix over chunks ----------------
__global__ __launch_bounds__(256) void prefix_kernel()
{
    const int gid = blockIdx.x * 256 + threadIdx.x;
    if (blockIdx.x < 256) {
        const int h = gid >> 12;
        const int e = gid & 4095;
        const size_t base0 = ((size_t)h * NCHUNK * NC) * DHEAD + e;
        const size_t cstep = (size_t)NC * DHEAD;
        float tk[NCHUNK], tv[NCHUNK];
#pragma unroll
        for (int ch = 0; ch < NCHUNK; ++ch) {
            tk[ch] = g_Tk[base0 + ch * cstep];
            tv[ch] = g_Tv[base0 + ch * cstep];
        }
        float rk = 0.f, rv = 0.f;
#pragma unroll
        for (int ch = 0; ch < NCHUNK; ++ch) {
            g_A0k[base0 + ch * cstep] = rk; rk += tk[ch];
            g_A0v[base0 + ch * cstep] = rv; rv += tv[ch];
        }
    } else {
        const int e = (blockIdx.x - 256) * 256 + threadIdx.x;  // h*NC + c
        const int h = e >> 6;
        const int c = e & 63;
        const size_t base0 = (size_t)h * NCHUNK * NC + c;
        float tn[NCHUNK];
#pragma unroll
        for (int ch = 0; ch < NCHUNK; ++ch) tn[ch] = g_Tn[base0 + ch * NC];
        float rn = 0.f;
#pragma unroll
        for (int ch = 0; ch < NCHUNK; ++ch) { g_N0[base0 + ch * NC] = rn; rn += tn[ch]; }
    }
}

// ---------------- per-(head,chunk) attention: 6-buffer overlay ---------
// Buffers (each [64][SP] floats) with phase-based reuse:
//   A: QsT  (G,P)      -> PT  (softmax, W, O)
//   B: KsT  (G)        -> A0kT (P)
//   C: cwsN (cumsum, W)
//   D: cwsT (P)        -> Vs  (O)
//   E: ncs  (P, softmax)-> A0v (O)
//   F: GT   (G->P, W->O)
#define ABUF (64 * SP)
#define ATT_SMEM ((6 * ABUF + 64) * 4)

__global__ __launch_bounds__(256, 2) void attn_kernel(const float* __restrict__ beta)
{
    extern __shared__ float smf[];
    float* bufA = smf;                 // QsT -> PT
    float* bufB = smf + ABUF;          // KsT -> A0kT
    float* bufC = smf + 2 * ABUF;      // cwsN
    float* bufD = smf + 3 * ABUF;      // cwsT -> Vs
    float* bufE = smf + 4 * ABUF;      // ncs -> A0v
    float* bufF = smf + 5 * ABUF;      // GT
    float* n0v  = smf + 6 * ABUF;

    const int h = blockIdx.y, ch = blockIdx.x;
    const int s0 = ch * CHUNK;
    const int tid = threadIdx.x;
    const int tx = tid & 15, ty = tid >> 4;
    const float qscale = 0.125f * expf(-beta[h]);
    const size_t abase = ((size_t)(h * NCHUNK + ch) * NC) * DHEAD;

    // phase 0: load QsT, KsT, cw (both orientations), n0v
    for (int e = tid; e < CHUNK * DHEAD; e += 256) {
        int r = e >> 6, d = e & 63;
        bufA[d * SP + r] = g_Q[(size_t)(s0 + r) * DMODEL + h * DHEAD + d] * qscale; // QsT[d][s]
        bufB[d * SP + r] = g_K[(size_t)(s0 + r) * DMODEL + h * DHEAD + d];          // KsT[d][t]
        float cv = g_cw[((size_t)h * NC + r) * SLEN + s0 + d];
        bufC[r * SP + d] = cv;   // cwsN[c][t]
        bufD[d * SP + r] = cv;   // cwsT[t][c]
    }
    if (tid < NC) n0v[tid] = g_N0[(size_t)(h * NCHUNK + ch) * NC + tid];
    __syncthreads();

    // ncs cumsum into bufE (not read until P step, which is after a sync)
    if (tid < NC) {
        float run = n0v[tid];
#pragma unroll
        for (int t = 0; t < CHUNK; ++t) { run += bufC[tid * SP + t]; bufE[tid * SP + t] = run; }
    }

    // G step: GT[t][s] = masked QsT . KsT
    {
        float acc[4][4];
#pragma unroll
        for (int i = 0; i < 4; ++i)
#pragma unroll
            for (int j = 0; j < 4; ++j) acc[i][j] = 0.f;
#pragma unroll 4
        for (int d = 0; d < DHEAD; ++d) {
            float4 a4 = *(const float4*)&bufA[d * SP + (ty << 2)];
            float4 b4 = *(const float4*)&bufB[d * SP + (tx << 2)];
            float ar[4] = {a4.x, a4.y, a4.z, a4.w};
            float br[4] = {b4.x, b4.y, b4.z, b4.w};
#pragma unroll
            for (int i = 0; i < 4; ++i)
#pragma unroll
                for (int j = 0; j < 4; ++j) acc[i][j] = fmaf(ar[i], br[j], acc[i][j]);
        }
#pragma unroll
        for (int i = 0; i < 4; ++i) {
            int s = (ty << 2) + i;
#pragma unroll
            for (int j = 0; j < 4; ++j) {
                int t = (tx << 2) + j;
                bufF[t * SP + s] = (t <= s) ? acc[i][j] : 0.f;
            }
        }
    }
    __syncthreads();   // KsT reads done; GT written

    // load A0kT into bufB (overwrites KsT)
    for (int e = tid; e < CHUNK * DHEAD; e += 256) {
        int r = e >> 6, d = e & 63;
        bufB[d * SP + r] = g_A0k[abase + e];   // A0kT[d][c]
    }
    __syncthreads();

    // P step: acc = QsT.A0kT + GT.cwsT ; PT[c][s] = acc / ncs[c][s] (PT overlays QsT)
    {
        float acc[4][4];
#pragma unroll
        for (int i = 0; i < 4; ++i)
#pragma unroll
            for (int j = 0; j < 4; ++j) acc[i][j] = 0.f;
#pragma unroll 4
        for (int d = 0; d < DHEAD; ++d) {
            float4 a4 = *(const float4*)&bufA[d * SP + (ty << 2)];
            float4 b4 = *(const float4*)&bufB[d * SP + (tx << 2)];
            float ar[4] = {a4.x, a4.y, a4.z, a4.w};
            float br[4] = {b4.x, b4.y, b4.z, b4.w};
#pragma unroll
            for (int i = 0; i < 4; ++i)
#pragma unroll
                for (int j = 0; j < 4; ++j) acc[i][j] = fmaf(ar[i], br[j], acc[i][j]);
        }
#pragma unroll 4
        for (int t = 0; t < CHUNK; ++t) {
            float4 a4 = *(const float4*)&bufF[t * SP + (ty << 2)];
            float4 b4 = *(const float4*)&bufD[t * SP + (tx << 2)];
            float ar[4] = {a4.x, a4.y, a4.z, a4.w};
            float br[4] = {b4.x, b4.y, b4.z, b4.w};
#pragma unroll
            for (int i = 0; i < 4; ++i)
#pragma unroll
                for (int j = 0; j < 4; ++j) acc[i][j] = fmaf(ar[i], br[j], acc[i][j]);
        }
        __syncthreads();   // all QsT reads done before PT overwrite
#pragma unroll
        for (int i = 0; i < 4; ++i) {
            int s = (ty << 2) + i;
#pragma unroll
            for (int j = 0; j < 4; ++j) {
                int c = (tx << 2) + j;
                bufA[c * SP + s] = acc[i][j] / bufE[c * SP + s];   // PT[c][s]
            }
        }
    }
    __syncthreads();

    // softmax over c per s, then /ncs
    if (tid < CHUNK) {
        int s = tid;
        float m = -INFINITY;
#pragma unroll
        for (int c = 0; c < NC; ++c) m = fmaxf(m, bufA[c * SP + s]);
        float sum = 0.f;
#pragma unroll
        for (int c = 0; c < NC; ++c) { float e = expf(bufA[c * SP + s] - m); bufA[c * SP + s] = e; sum += e; }
        float inv = 1.f / sum;
#pragma unroll
        for (int c = 0; c < NC; ++c) bufA[c * SP + s] = bufA[c * SP + s] * inv / bufE[c * SP + s];
    }
    __syncthreads();   // ncs + cwsT dead after this point

    // load Vs into bufD (over cwsT), A0v into bufE (over ncs)
    for (int e = tid; e < CHUNK * DHEAD; e += 256) {
        int r = e >> 6, d = e & 63;
        bufD[r * SP + d] = g_V[(size_t)(s0 + r) * DMODEL + h * DHEAD + d];  // Vs[t][d]
        bufE[r * SP + d] = g_A0v[abase + e];                                 // A0v[c][d]
    }
    __syncthreads();

    // W step: GT[t][s] = masked sum_c PT[c][s]*cwsN[c][t]
    {
        float acc[4][4];
#pragma unroll
        for (int i = 0; i < 4; ++i)
#pragma unroll
            for (int j = 0; j < 4; ++j) acc[i][j] = 0.f;
#pragma unroll 4
        for (int c = 0; c < NC; ++c) {
            float4 a4 = *(const float4*)&bufA[c * SP + (ty << 2)];
            float4 b4 = *(const float4*)&bufC[c * SP + (tx << 2)];
            float ar[4] = {a4.x, a4.y, a4.z, a4.w};
            float br[4] = {b4.x, b4.y, b4.z, b4.w};
#pragma unroll
            for (int i = 0; i < 4; ++i)
#pragma unroll
                for (int j = 0; j < 4; ++j) acc[i][j] = fmaf(ar[i], br[j], acc[i][j]);
        }
        __syncthreads();
#pragma unroll
        for (int i = 0; i < 4; ++i) {
            int s = (ty << 2) + i;
#pragma unroll
            for (int j = 0; j < 4; ++j) {
                int t = (tx << 2) + j;
                bufF[t * SP + s] = (t <= s) ? acc[i][j] : 0.f;
            }
        }
    }
    __syncthreads();

    // O step
    {
        float acc[4][4];
#pragma unroll
        for (int i = 0; i < 4; ++i)
#pragma unroll
            for (int j = 0; j < 4; ++j) acc[i][j] = 0.f;
#pragma unroll 4
        for (int t = 0; t < CHUNK; ++t) {
            float4 a4 = *(const float4*)&bufF[t * SP + (ty << 2)];
            float4 b4 = *(const float4*)&bufD[t * SP + (tx << 2)];
            float ar[4] = {a4.x, a4.y, a4.z, a4.w};
            float br[4] = {b4.x, b4.y, b4.z, b4.w};
#pragma unroll
            for (int i = 0; i < 4; ++i)
#pragma unroll
                for (int j = 0; j < 4; ++j) acc[i][j] = fmaf(ar[i], br[j], acc[i][j]);
        }
#pragma unroll 4
        for (int c = 0; c < NC; ++c) {
            float4 a4 = *(const float4*)&bufA[c * SP + (ty << 2)];
            float4 b4 = *(const float4*)&bufE[c * SP + (tx << 2)];
            float ar[4] = {a4.x, a4.y, a4.z, a4.w};
            float br[4] = {b4.x, b4.y, b4.z, b4.w};
#pragma unroll
            for (int i = 0; i < 4; ++i)
#pragma unroll
                for (int j = 0; j < 4; ++j) acc[i][j] = fmaf(ar[i], br[j], acc[i][j]);
        }
#pragma unroll
        for (int i = 0; i < 4; ++i) {
            int s = (ty << 2) + i;
            size_t rowoff = (size_t)(s0 + s) * DMODEL + h * DHEAD + (tx << 2);
            __nv_bfloat16 h0 = __float2bfloat16_rn(acc[i][0]);
            __nv_bfloat16 h1 = __float2bfloat16_rn(acc[i][1]);
            __nv_bfloat16 h2 = __float2bfloat16_rn(acc[i][2]);
            __nv_bfloat16 h3 = __float2bfloat16_rn(acc[i][3]);
            *(uint32_t*)&g_Oh[rowoff]     = pack_bf2(h0, h1);
            *(uint32_t*)&g_Oh[rowoff + 2] = pack_bf2(h2, h3);
            *(uint32_t*)&g_Ol[rowoff] =
                pack_bf2(__float2bfloat16_rn(acc[i][0] - __bfloat162float(h0)),
                         __float2bfloat16_rn(acc[i][1] - __bfloat162float(h1)));
            *(uint32_t*)&g_Ol[rowoff + 2] =
                pack_bf2(__float2bfloat16_rn(acc[i][2] - __bfloat162float(h2)),
                         __float2bfloat16_rn(acc[i][3] - __bfloat162float(h3)));
        }
    }
}

// ---------------- launch -----------------------------------------------
extern "C" void kernel_launch(void* const* d_in, const int* in_sizes, int n_in,
                              void* d_out, int out_size)
{
    const float* x    = (const float*)d_in[0];
    const float* q_c  = (const float*)d_in[1];
    const float* beta = (const float*)d_in[2];
    const float* Wq   = (const float*)d_in[3];
    const float* bq   = (const float*)d_in[4];
    const float* Wk   = (const float*)d_in[5];
    const float* bk   = (const float*)d_in[6];
    const float* Wv   = (const float*)d_in[7];
    const float* bv   = (const float*)d_in[8];
    const float* Wo   = (const float*)d_in[9];
    const float* bo   = (const float*)d_in[10];
    float* out = (float*)d_out;

    static bool inited = false;
    static cudaStream_t s2;
    static cudaEvent_t evFork, evQ, evWo;
    if (!inited) {
        cudaFuncSetAttribute(attn_kernel, cudaFuncAttributeMaxDynamicSharedMemorySize,
                             ATT_SMEM);
        cudaFuncSetAttribute(chunksum_kernel, cudaFuncAttributeMaxDynamicSharedMemorySize,
                             (int)sizeof(ChunkSmem));
        cudaFuncSetAttribute(tc_gemm_kv_kernel, cudaFuncAttributeMaxDynamicSharedMemorySize, GSMEM128);
        cudaFuncSetAttribute(tc_gemm_q_kernel, cudaFuncAttributeMaxDynamicSharedMemorySize, GSMEM128);
        cudaFuncSetAttribute(tc_gemm_o_kernel, cudaFuncAttributeMaxDynamicSharedMemorySize, GSMEM64);
        cudaStreamCreateWithFlags(&s2, cudaStreamNonBlocking);
        cudaEventCreateWithFlags(&evFork, cudaEventDisableTiming);
        cudaEventCreateWithFlags(&evQ, cudaEventDisableTiming);
        cudaEventCreateWithFlags(&evWo, cudaEventDisableTiming);
        inited = true;
    }

    // main stream: split (x, Wq, Wk, Wv) then KV GEMM
    split4_kernel<<<dim3(1024, 4), 256>>>(x, Wq, Wk, Wv);
    tc_gemm_kv_kernel<<<dim3(8, 8, 2), 256, GSMEM128>>>(bk, bv);

    // fork AFTER the KV GEMM: Q GEMM overlaps chunksum/prefix
    cudaEventRecord(evFork, 0);
    cudaStreamWaitEvent(s2, evFork, 0);
    tc_gemm_q_kernel<<<dim3(8, 8), 256, GSMEM128, s2>>>(bq);
    cudaEventRecord(evQ, s2);
    splitWo_kernel<<<1024, 256, 0, s2>>>(Wo);
    cudaEventRecord(evWo, s2);

    // main stream: chunksum + prefix
    chunksum_kernel<<<dim3(NCHUNK, NHEAD), 256, sizeof(ChunkSmem)>>>(q_c);
    prefix_kernel<<<260, 256>>>();

    // join
    cudaStreamWaitEvent(0, evQ, 0);
    attn_kernel<<<dim3(NCHUNK, NHEAD), 256, ATT_SMEM>>>(beta);
    cudaStreamWaitEvent(0, evWo, 0);
    tc_gemm_o_kernel<<<dim3(8, 16), 256, GSMEM64>>>(bo, out);
}